// round 9
// baseline (speedup 1.0000x reference)
#include <cuda_runtime.h>
#include <cuda_bf16.h>
#include <cstdint>

// Problem constants (shapes fixed by the dataset)
#define NUM_NODES   10000
#define FEAT        128
#define CAP         256          // per-node edge-list capacity (deg ~ Poisson(64))

// Scratch (no cudaMalloc allowed) — device globals. No float atomics anywhere.
__device__ int   g_cnt[NUM_NODES];
__device__ int   g_elist[NUM_NODES * CAP];
__device__ __align__(16) float g_y[NUM_NODES * FEAT];   // y = x @ W^T

// ---------------------------------------------------------------------------
// packed f32x2 helpers (sm_100+): one instruction = two independent FMAs
// ---------------------------------------------------------------------------
__device__ __forceinline__ unsigned long long fma2(unsigned long long a,
                                                   unsigned long long b,
                                                   unsigned long long c) {
    unsigned long long d;
    asm("fma.rn.f32x2 %0, %1, %2, %3;" : "=l"(d) : "l"(a), "l"(b), "l"(c));
    return d;
}
__device__ __forceinline__ unsigned long long packf2(float x, float y) {
    unsigned long long r;
    asm("mov.b64 %0, {%1, %2};" : "=l"(r) : "f"(x), "f"(y));
    return r;
}
__device__ __forceinline__ float2 unpackf2(unsigned long long v) {
    float2 r;
    asm("mov.b64 {%0, %1}, %2;" : "=f"(r.x), "=f"(r.y) : "l"(v));
    return r;
}

// ---------------------------------------------------------------------------
// Kernel 0: zero the per-node counters (must run every launch: graph replay)
// ---------------------------------------------------------------------------
__global__ void zero_kernel() {
    int i = blockIdx.x * blockDim.x + threadIdx.x;
    if (i < NUM_NODES) g_cnt[i] = 0;
}

// ---------------------------------------------------------------------------
// Kernel 1: build adjacency lists. One thread per edge; scalar int atomics only.
// edge_index is int32 on device (JAX default config downcasts int64).
// ---------------------------------------------------------------------------
__global__ void fill_kernel(const int* __restrict__ ei, int nedges, int nnodes) {
    int e = blockIdx.x * blockDim.x + threadIdx.x;
    if (e >= nedges) return;
    int src = ei[e];
    int dst = ei[nedges + e];
    if ((unsigned)src >= (unsigned)nnodes || (unsigned)dst >= (unsigned)nnodes)
        return;
    int pos = atomicAdd(&g_cnt[dst], 1);
    if (pos < CAP) g_elist[dst * CAP + pos] = src;
}

// ---------------------------------------------------------------------------
// Kernel 2: y = x @ W^T (no bias/relu — fused into gather).
// 512 threads (16 warps), 80 rows/block -> 125 blocks = one wave.
// W stored column-PAIRED in smem: pair p (0..63) = output cols (p, p+64),
//   Wp[p*260 + 2d + {0,1}] = (W[p][d], W[p+64][d]); stride 260 -> bank 4*cg,
//   conflict-free 8-lane LDS.128 phases.
// Thread (cg=lane, rg=warp): pairs cg & cg+32; rows rg*5..rg*5+4.
// Inner: packed fma.rn.f32x2 -> 2 FMAs/instr on the fma pipe.
// ---------------------------------------------------------------------------
#define RPB 80
#define RPW 5
#define WP_STRIDE 260
#define GEMM_SMEM ((64 * WP_STRIDE + RPB * FEAT) * 4)   // 66560 + 40960 B

__global__ __launch_bounds__(512, 1)
void gemm_kernel(const float* __restrict__ x,
                 const float* __restrict__ W,
                 float* __restrict__ y,
                 int nnodes) {
    extern __shared__ float smem[];
    float* Wp = smem;                     // 64 pairs x 260
    float* xs = smem + 64 * WP_STRIDE;    // [80][128]

    int row0 = blockIdx.x * RPB;
    int t = threadIdx.x;

    // Stage W, pairing columns (p, p+64)
    for (int i = t; i < 64 * FEAT; i += 512) {
        int p = i >> 7;
        int d = i & 127;
        Wp[p * WP_STRIDE + 2 * d]     = W[p * FEAT + d];
        Wp[p * WP_STRIDE + 2 * d + 1] = W[(p + 64) * FEAT + d];
    }

    // Stage x tile (float4, coalesced)
    for (int i = t; i < RPB * (FEAT / 4); i += 512) {
        int n  = i >> 5;
        int d4 = i & 31;
        int node = row0 + n;
        float4 v = make_float4(0.f, 0.f, 0.f, 0.f);
        if (node < nnodes)
            v = ((const float4*)(x + (long)node * FEAT))[d4];
        ((float4*)xs)[i] = v;
    }
    __syncthreads();

    int cg = t & 31;
    int rg = t >> 5;

    const ulonglong2* WA = (const ulonglong2*)(Wp + cg * WP_STRIDE);        // cols (cg, cg+64)
    const ulonglong2* WB = (const ulonglong2*)(Wp + (cg + 32) * WP_STRIDE); // cols (cg+32, cg+96)

    unsigned long long accA[RPW], accB[RPW];
#pragma unroll
    for (int r = 0; r < RPW; r++) { accA[r] = 0ull; accB[r] = 0ull; }

#pragma unroll 4
    for (int d4 = 0; d4 < FEAT / 4; d4++) {
        ulonglong2 a01 = WA[d4 * 2];       // w pairs for k=0,1
        ulonglong2 a23 = WA[d4 * 2 + 1];   // k=2,3
        ulonglong2 b01 = WB[d4 * 2];
        ulonglong2 b23 = WB[d4 * 2 + 1];
#pragma unroll
        for (int r = 0; r < RPW; r++) {
            float4 h = *(const float4*)&xs[(rg * RPW + r) * FEAT + d4 * 4];
            unsigned long long h0 = packf2(h.x, h.x);
            unsigned long long h1 = packf2(h.y, h.y);
            unsigned long long h2 = packf2(h.z, h.z);
            unsigned long long h3 = packf2(h.w, h.w);
            accA[r] = fma2(h0, a01.x, accA[r]);
            accA[r] = fma2(h1, a01.y, accA[r]);
            accA[r] = fma2(h2, a23.x, accA[r]);
            accA[r] = fma2(h3, a23.y, accA[r]);
            accB[r] = fma2(h0, b01.x, accB[r]);
            accB[r] = fma2(h1, b01.y, accB[r]);
            accB[r] = fma2(h2, b23.x, accB[r]);
            accB[r] = fma2(h3, b23.y, accB[r]);
        }
    }

#pragma unroll
    for (int r = 0; r < RPW; r++) {
        int node = row0 + rg * RPW + r;
        if (node < nnodes) {
            float2 va = unpackf2(accA[r]);
            float2 vb = unpackf2(accB[r]);
            float* yr = y + (long)node * FEAT;
            yr[cg]      = va.x;
            yr[cg + 64] = va.y;
            yr[cg + 32] = vb.x;
            yr[cg + 96] = vb.y;
        }
    }
}

// ---------------------------------------------------------------------------
// Kernel 3: gather-aggregate over y, fused bias+relu, writes out directly.
// out[n] = relu(y[n] + (sum_{src in adj(n)} y[src]) / max(deg,1) + b)
// One warp per node; lane = one float4 chunk. y is L2-resident.
// ---------------------------------------------------------------------------
__global__ void gather_kernel(const float* __restrict__ y,
                              const float* __restrict__ b,
                              float* __restrict__ out, int nnodes) {
    int idx  = blockIdx.x * blockDim.x + threadIdx.x;
    int node = idx >> 5;
    int lane = idx & 31;
    if (node >= nnodes) return;

    int deg = g_cnt[node];
    int m   = deg < CAP ? deg : CAP;
    const int* __restrict__ lst = g_elist + node * CAP;

    float4 acc = make_float4(0.f, 0.f, 0.f, 0.f);
#pragma unroll 4
    for (int i = 0; i < m; i++) {
        int src = __ldg(&lst[i]);   // warp-uniform -> broadcast
        float4 v = __ldg(((const float4*)(y + (long)src * FEAT)) + lane);
        acc.x += v.x; acc.y += v.y; acc.z += v.z; acc.w += v.w;
    }

    float inv = 1.0f / fmaxf((float)deg, 1.0f);
    float4 yr = __ldg(((const float4*)(y + (long)node * FEAT)) + lane);
    float4 bb = __ldg(((const float4*)b) + lane);
    float4 o;
    o.x = fmaxf(acc.x * inv + yr.x + bb.x, 0.0f);
    o.y = fmaxf(acc.y * inv + yr.y + bb.y, 0.0f);
    o.z = fmaxf(acc.z * inv + yr.z + bb.z, 0.0f);
    o.w = fmaxf(acc.w * inv + yr.w + bb.w, 0.0f);
    ((float4*)(out + (long)node * FEAT))[lane] = o;
}

// ---------------------------------------------------------------------------
// Launch: zero -> fill -> gemm -> gather (stream-ordered on capture stream)
// ---------------------------------------------------------------------------
extern "C" void kernel_launch(void* const* d_in, const int* in_sizes, int n_in,
                              void* d_out, int out_size) {
    const float* x  = (const float*)d_in[0];
    const int*   ei = (const int*)d_in[1];   // int32 (JAX default x64-disabled)
    const float* W  = (const float*)d_in[2];
    const float* b  = (const float*)d_in[3];
    float*       out = (float*)d_out;

    int nnodes = in_sizes[0] / FEAT;
    int nedges = in_sizes[1] / 2;

    cudaFuncSetAttribute(gemm_kernel,
                         cudaFuncAttributeMaxDynamicSharedMemorySize,
                         GEMM_SMEM);

    zero_kernel<<<(NUM_NODES + 255) / 256, 256>>>();

    fill_kernel<<<(nedges + 255) / 256, 256>>>(ei, nedges, nnodes);

    {
        int blocks = (nnodes + RPB - 1) / RPB;
        gemm_kernel<<<blocks, 512, GEMM_SMEM>>>(x, W, g_y, nnodes);
    }
    {
        long threads = (long)nnodes * 32;
        int blocks = (int)((threads + 255) / 256);
        gather_kernel<<<blocks, 256>>>(g_y, b, out, nnodes);
    }
}